// round 3
// baseline (speedup 1.0000x reference)
#include <cuda_runtime.h>
#include <cstdint>

#define MROWS 16384
#define CDIM  1024
#define TSEQ  2048
#define BBAT  8
#define HHEAD 16
#define NKIT  (CDIM/8)

// ---------------- scratch (static __device__ allocations only) ----------------
__device__ float g_r  [(size_t)MROWS*CDIM];
__device__ float g_k  [(size_t)MROWS*CDIM];
__device__ float g_v  [(size_t)MROWS*CDIM];
__device__ float g_g  [(size_t)MROWS*CDIM];
__device__ float g_wkv[(size_t)MROWS*CDIM];
__device__ float2 g_stats[BBAT*HHEAD];
__device__ float g_state_scratch[BBAT*HHEAD*64*64];

__device__ __forceinline__ float sigf(float x){ return 1.0f/(1.0f+__expf(-x)); }

__device__ __forceinline__ void split_tf32(float a, uint32_t& hi, uint32_t& lo){
    uint32_t h;
    asm("cvt.rna.tf32.f32 %0, %1;" : "=r"(h) : "f"(a));
    hi = h;
    lo = __float_as_uint(a - __uint_as_float(h));
}

__device__ __forceinline__ void mma_tf32(float* c, const uint32_t* a, const uint32_t* b){
    asm volatile("mma.sync.aligned.m16n8k8.row.col.f32.tf32.tf32.f32 "
        "{%0,%1,%2,%3}, {%4,%5,%6,%7}, {%8,%9}, {%0,%1,%2,%3};"
        : "+f"(c[0]), "+f"(c[1]), "+f"(c[2]), "+f"(c[3])
        : "r"(a[0]), "r"(a[1]), "r"(a[2]), "r"(a[3]), "r"(b[0]), "r"(b[1]));
}

// =====================================================================
// tf32x3 GEMM, hi/lo split done ONCE in the smem loader.
// AMODE 0: fused 4-projection kernel, z=blockIdx.z picks W/mix/bias/act,
//          A = x*mix + x_shift*(1-mix).
// AMODE 1: A = groupnorm(g_wkv) (stats from scan), epilogue *g_g -> out.
// Block 128x128, 4 warps (2x2 of 64x64), BK=8, double-buffered smem.
// smem layout [m][12] (stride 12 -> conflict-free frag loads, STS.128 stores)
// =====================================================================
template<int AMODE>
__global__ __launch_bounds__(128, 2)
void mma_gemm(const float* __restrict__ x,
              const float* __restrict__ W0, const float* __restrict__ W1,
              const float* __restrict__ W2, const float* __restrict__ W3,
              const float* __restrict__ b0p, const float* __restrict__ b1p,
              const float* __restrict__ b2p, const float* __restrict__ b3p,
              const float* __restrict__ m0p, const float* __restrict__ m1p,
              const float* __restrict__ m2p, const float* __restrict__ m3p,
              const float* __restrict__ gnw, const float* __restrict__ gnb,
              float* __restrict__ out_ext)
{
    __shared__ uint32_t As_hi[2][128][12];
    __shared__ uint32_t As_lo[2][128][12];
    __shared__ uint32_t Bs_hi[2][128][12];
    __shared__ uint32_t Bs_lo[2][128][12];

    const int z = (AMODE==0) ? blockIdx.z : 0;
    const float* W    = (AMODE==0) ? (z==0?W0:z==1?W1:z==2?W2:W3) : W0;
    const float* bias = (AMODE==0) ? (z==0?b0p:z==1?b1p:z==2?b2p:b3p) : b0p;
    const float* mix  = (AMODE==0) ? (z==0?m0p:z==1?m1p:z==2?m2p:m3p) : nullptr;
    float* out        = (AMODE==0) ? (z==0?g_r:z==1?g_k:z==2?g_v:g_g) : out_ext;

    const int tid=threadIdx.x, lane=tid&31, warp=tid>>5;
    const int warpM=warp>>1, warpN=warp&1;
    const int bm=blockIdx.y, bn=blockIdx.x;
    const int g4=lane>>2, t4=lane&3;

    const int gm = bm*128 + tid;   // A row loaded by this thread
    const int gn = bn*128 + tid;   // W row loaded by this thread
    const bool hs = (AMODE==0) && ((gm & (TSEQ-1)) != 0);

    float4 ra0, ra1, rb0, rb1;

    auto load_regs = [&](int kt){
        const int ko = kt*8;
        rb0 = *(const float4*)(W + (size_t)gn*CDIM + ko);
        rb1 = *(const float4*)(W + (size_t)gn*CDIM + ko + 4);
        if (AMODE==0){
            float4 xa0 = *(const float4*)(x + (size_t)gm*CDIM + ko);
            float4 xa1 = *(const float4*)(x + (size_t)gm*CDIM + ko + 4);
            float4 mv0 = *(const float4*)(mix + ko);
            float4 mv1 = *(const float4*)(mix + ko + 4);
            float4 xs0 = make_float4(0,0,0,0), xs1 = make_float4(0,0,0,0);
            if (hs){
                xs0 = *(const float4*)(x + (size_t)(gm-1)*CDIM + ko);
                xs1 = *(const float4*)(x + (size_t)(gm-1)*CDIM + ko + 4);
            }
            ra0.x = xa0.x*mv0.x + xs0.x*(1.0f-mv0.x);
            ra0.y = xa0.y*mv0.y + xs0.y*(1.0f-mv0.y);
            ra0.z = xa0.z*mv0.z + xs0.z*(1.0f-mv0.z);
            ra0.w = xa0.w*mv0.w + xs0.w*(1.0f-mv0.w);
            ra1.x = xa1.x*mv1.x + xs1.x*(1.0f-mv1.x);
            ra1.y = xa1.y*mv1.y + xs1.y*(1.0f-mv1.y);
            ra1.z = xa1.z*mv1.z + xs1.z*(1.0f-mv1.z);
            ra1.w = xa1.w*mv1.w + xs1.w*(1.0f-mv1.w);
        } else {
            float4 w0 = *(const float4*)(g_wkv + (size_t)gm*CDIM + ko);
            float4 w1 = *(const float4*)(g_wkv + (size_t)gm*CDIM + ko + 4);
            const int bh = (gm >> 11)*HHEAD + (ko >> 6);
            const float2 st = g_stats[bh];
            float4 gw0 = *(const float4*)(gnw + ko);
            float4 gw1 = *(const float4*)(gnw + ko + 4);
            float4 gb0 = *(const float4*)(gnb + ko);
            float4 gb1 = *(const float4*)(gnb + ko + 4);
            ra0.x = (w0.x - st.x)*st.y*gw0.x + gb0.x;
            ra0.y = (w0.y - st.x)*st.y*gw0.y + gb0.y;
            ra0.z = (w0.z - st.x)*st.y*gw0.z + gb0.z;
            ra0.w = (w0.w - st.x)*st.y*gw0.w + gb0.w;
            ra1.x = (w1.x - st.x)*st.y*gw1.x + gb1.x;
            ra1.y = (w1.y - st.x)*st.y*gw1.y + gb1.y;
            ra1.z = (w1.z - st.x)*st.y*gw1.z + gb1.z;
            ra1.w = (w1.w - st.x)*st.y*gw1.w + gb1.w;
        }
    };

    auto split_store = [&](int buf){
        uint32_t h[8], l[8];
        split_tf32(ra0.x,h[0],l[0]); split_tf32(ra0.y,h[1],l[1]);
        split_tf32(ra0.z,h[2],l[2]); split_tf32(ra0.w,h[3],l[3]);
        split_tf32(ra1.x,h[4],l[4]); split_tf32(ra1.y,h[5],l[5]);
        split_tf32(ra1.z,h[6],l[6]); split_tf32(ra1.w,h[7],l[7]);
        *(uint4*)&As_hi[buf][tid][0] = make_uint4(h[0],h[1],h[2],h[3]);
        *(uint4*)&As_hi[buf][tid][4] = make_uint4(h[4],h[5],h[6],h[7]);
        *(uint4*)&As_lo[buf][tid][0] = make_uint4(l[0],l[1],l[2],l[3]);
        *(uint4*)&As_lo[buf][tid][4] = make_uint4(l[4],l[5],l[6],l[7]);
        split_tf32(rb0.x,h[0],l[0]); split_tf32(rb0.y,h[1],l[1]);
        split_tf32(rb0.z,h[2],l[2]); split_tf32(rb0.w,h[3],l[3]);
        split_tf32(rb1.x,h[4],l[4]); split_tf32(rb1.y,h[5],l[5]);
        split_tf32(rb1.z,h[6],l[6]); split_tf32(rb1.w,h[7],l[7]);
        *(uint4*)&Bs_hi[buf][tid][0] = make_uint4(h[0],h[1],h[2],h[3]);
        *(uint4*)&Bs_hi[buf][tid][4] = make_uint4(h[4],h[5],h[6],h[7]);
        *(uint4*)&Bs_lo[buf][tid][0] = make_uint4(l[0],l[1],l[2],l[3]);
        *(uint4*)&Bs_lo[buf][tid][4] = make_uint4(l[4],l[5],l[6],l[7]);
    };

    float c[4][8][4];
    #pragma unroll
    for (int i=0;i<4;i++)
        #pragma unroll
        for (int j=0;j<8;j++){ c[i][j][0]=0.f;c[i][j][1]=0.f;c[i][j][2]=0.f;c[i][j][3]=0.f; }

    load_regs(0);
    split_store(0);
    load_regs(1);

    for (int kt=0; kt<NKIT; kt++){
        __syncthreads();
        const int buf = kt & 1;
        if (kt+1 < NKIT) split_store((kt+1)&1);
        if (kt+2 < NKIT) load_regs(kt+2);

        uint32_t ah[4][4], al[4][4], bh_[8][2], bl_[8][2];
        #pragma unroll
        for (int mt=0; mt<4; mt++){
            const int m = warpM*64 + mt*16 + g4;
            ah[mt][0]=As_hi[buf][m  ][t4];   al[mt][0]=As_lo[buf][m  ][t4];
            ah[mt][1]=As_hi[buf][m+8][t4];   al[mt][1]=As_lo[buf][m+8][t4];
            ah[mt][2]=As_hi[buf][m  ][t4+4]; al[mt][2]=As_lo[buf][m  ][t4+4];
            ah[mt][3]=As_hi[buf][m+8][t4+4]; al[mt][3]=As_lo[buf][m+8][t4+4];
        }
        #pragma unroll
        for (int nt=0; nt<8; nt++){
            const int n = warpN*64 + nt*8 + g4;
            bh_[nt][0]=Bs_hi[buf][n][t4];   bl_[nt][0]=Bs_lo[buf][n][t4];
            bh_[nt][1]=Bs_hi[buf][n][t4+4]; bl_[nt][1]=Bs_lo[buf][n][t4+4];
        }
        #pragma unroll
        for (int mt=0; mt<4; mt++)
            #pragma unroll
            for (int nt=0; nt<8; nt++){
                mma_tf32(c[mt][nt], ah[mt], bh_[nt]);
                mma_tf32(c[mt][nt], ah[mt], bl_[nt]);
                mma_tf32(c[mt][nt], al[mt], bh_[nt]);
            }
    }

    // ---- epilogue ----
    #pragma unroll
    for (int mt=0; mt<4; mt++){
        const int r0 = bm*128 + warpM*64 + mt*16 + g4;
        const int r1 = r0 + 8;
        #pragma unroll
        for (int nt=0; nt<8; nt++){
            const int col = bn*128 + warpN*64 + nt*8 + t4*2;
            const float2 bb = *(const float2*)(bias + col);
            float v0 = c[mt][nt][0] + bb.x;
            float v1 = c[mt][nt][1] + bb.y;
            float v2 = c[mt][nt][2] + bb.x;
            float v3 = c[mt][nt][3] + bb.y;
            if (AMODE==0){
                if (z==0){ v0=sigf(v0); v1=sigf(v1); v2=sigf(v2); v3=sigf(v3); }
                else if (z==3){ v0*=sigf(v0); v1*=sigf(v1); v2*=sigf(v2); v3*=sigf(v3); }
            } else {
                float2 g0 = *(const float2*)(g_g + (size_t)r0*CDIM + col);
                float2 g1 = *(const float2*)(g_g + (size_t)r1*CDIM + col);
                v0*=g0.x; v1*=g0.y; v2*=g1.x; v3*=g1.y;
            }
            *(float2*)(out + (size_t)r0*CDIM + col) = make_float2(v0,v1);
            *(float2*)(out + (size_t)r1*CDIM + col) = make_float2(v2,v3);
        }
    }
}

// ---------------- per-(token,head) L2 normalization of k and v -----------------
__global__ void l2norm_kernel()
{
    const int gwarp = (blockIdx.x*blockDim.x + threadIdx.x) >> 5;
    const int lane  = threadIdx.x & 31;
    float* arr = (blockIdx.y == 0) ? g_k : g_v;
    const size_t off = (size_t)gwarp*64;
    float v0 = arr[off+lane], v1 = arr[off+lane+32];
    float ss = v0*v0 + v1*v1;
    #pragma unroll
    for (int o=16;o;o>>=1) ss += __shfl_xor_sync(0xffffffffu, ss, o);
    const float n  = sqrtf(ss);
    const float sc = 1.0f/fmaxf(n, 1e-12f);
    arr[off+lane]    = v0*sc;
    arr[off+lane+32] = v1*sc;
}

// ---------------- sequential delta-rule scan: 1 CTA (128 thr) per (b,h) --------
// Thread t owns half a state row. Deferred scalar c (S_actual = c*S).
// ONE __syncthreads per step: k/r/v triple-buffered in smem, reduction
// results buffered per-step.
__global__ __launch_bounds__(128)
void scan_kernel(const float* __restrict__ decay, const float* __restrict__ eta,
                 float* __restrict__ state_out)
{
    const int bh = blockIdx.x;
    const int b = bh >> 4, h = bh & 15;
    const int t_ = threadIdx.x;
    const int row = t_ >> 1, half = t_ & 1;
    const int lane = t_ & 31, wid = t_ >> 5;
    const int koff = half*32;
    __shared__ __align__(16) float sk[3][64], sr[3][64], sv[3][64];
    __shared__ float red[3][4];
    __shared__ double redd[4][2];

    float S[32];
    #pragma unroll
    for (int j=0;j<32;j++) S[j]=0.f;
    float c = 1.0f;
    const float dec = 1.0f/(1.0f+expf(-decay[h]));
    const float et  = 1.0f/(1.0f+expf(-eta[h]));
    const float maxn = 16.0f;
    double wsum = 0.0, wsq = 0.0;

    const size_t base = (size_t)b*TSEQ*CDIM + (size_t)h*64;
    const float* kp = g_k + base;
    const float* rp = g_r + base;
    const float* vp = g_v + base;
    float*       op = g_wkv + base;

    // stage t=0 into buffer 0; prefetch t=1 into regs
    if (t_ < 64){ sk[0][t_] = kp[t_]; sv[0][t_] = vp[t_]; }
    else        { sr[0][t_-64] = rp[t_-64]; }
    float nk=0.f, nr=0.f, nv=0.f;
    if (t_ < 64){ nk = kp[CDIM+t_]; nv = vp[CDIM+t_]; }
    else        { nr = rp[CDIM+t_-64]; }
    __syncthreads();

    int buf = 0;
    for (int t=0; t<TSEQ; t++){
        const int nbuf = (buf==2) ? 0 : buf+1;
        // ---- pre-sync phase: uses step-t data in sk/sv[buf] ----
        const float4* k4 = (const float4*)(&sk[buf][koff]);
        float q0=0,q1=0,q2=0,q3=0;
        #pragma unroll
        for (int j=0;j<8;j++){
            float4 kv = k4[j];
            q0 = fmaf(S[4*j+0], kv.x, q0);
            q1 = fmaf(S[4*j+1], kv.y, q1);
            q2 = fmaf(S[4*j+2], kv.z, q2);
            q3 = fmaf(S[4*j+3], kv.w, q3);
        }
        float qp = (q0+q1)+(q2+q3);
        qp += __shfl_xor_sync(0xffffffffu, qp, 1);
        const float vi   = sv[buf][row];
        const float err  = c*qp - vi;
        const float c1   = dec*c;
        const float coef = (et*err)/c1;
        float s0=0,s1=0,s2=0,s3=0;
        #pragma unroll
        for (int j=0;j<8;j++){
            float4 kv = k4[j];
            float u0 = fmaf(-coef, kv.x, S[4*j+0]); S[4*j+0]=u0; s0 = fmaf(u0,u0,s0);
            float u1 = fmaf(-coef, kv.y, S[4*j+1]); S[4*j+1]=u1; s1 = fmaf(u1,u1,s1);
            float u2 = fmaf(-coef, kv.z, S[4*j+2]); S[4*j+2]=u2; s2 = fmaf(u2,u2,s2);
            float u3 = fmaf(-coef, kv.w, S[4*j+3]); S[4*j+3]=u3; s3 = fmaf(u3,u3,s3);
        }
        float ss = (s0+s1)+(s2+s3);
        #pragma unroll
        for (int o=16;o;o>>=1) ss += __shfl_xor_sync(0xffffffffu, ss, o);
        if (lane==0) red[buf][wid]=ss;
        // stage step t+1 into nbuf; prefetch step t+2
        if (t+1 < TSEQ){
            if (t_ < 64){ sk[nbuf][t_]=nk; sv[nbuf][t_]=nv; }
            else        { sr[nbuf][t_-64]=nr; }
        }
        if (t+2 < TSEQ){
            if (t_ < 64){ nk = kp[2*CDIM+t_]; nv = vp[2*CDIM+t_]; }
            else        { nr = rp[2*CDIM+t_-64]; }
        }
        __syncthreads();
        // ---- post-sync phase ----
        const float tot = red[buf][0]+red[buf][1]+red[buf][2]+red[buf][3];
        const float nrm = c1*sqrtf(tot);
        c = (nrm > maxn) ? c1*(maxn/nrm) : c1;
        const float4* r4 = (const float4*)(&sr[buf][koff]);
        float w0=0,w1=0,w2=0,w3=0;
        #pragma unroll
        for (int j=0;j<8;j++){
            float4 rv = r4[j];
            w0 = fmaf(S[4*j+0], rv.x, w0);
            w1 = fmaf(S[4*j+1], rv.y, w1);
            w2 = fmaf(S[4*j+2], rv.z, w2);
            w3 = fmaf(S[4*j+3], rv.w, w3);
        }
        float wpart = (w0+w1)+(w2+w3);
        wpart += __shfl_xor_sync(0xffffffffu, wpart, 1);
        const float wv = c*wpart;
        if (half==0) op[row] = wv;
        wsum += (double)wv;              // both halves accumulate -> /2 later
        wsq  += (double)wv*(double)wv;
        if ((t & 31)==31){
            #pragma unroll
            for (int j=0;j<32;j++) S[j]*=c;
            c = 1.0f;
        }
        kp += CDIM; rp += CDIM; vp += CDIM; op += CDIM;
        buf = nbuf;
    }
    // group-norm stats over (T, D) for this (b,h)
    double a1=wsum, a2=wsq;
    #pragma unroll
    for (int o=16;o;o>>=1){
        a1 += __shfl_xor_sync(0xffffffffu, a1, o);
        a2 += __shfl_xor_sync(0xffffffffu, a2, o);
    }
    if (lane==0){ redd[wid][0]=a1; redd[wid][1]=a2; }
    __syncthreads();
    if (t_==0){
        const double t1 = redd[0][0]+redd[1][0]+redd[2][0]+redd[3][0];
        const double t2 = redd[0][1]+redd[1][1]+redd[2][1]+redd[3][1];
        const double cnt = 2.0*(double)TSEQ*64.0;
        const double mean = t1 / cnt;
        const double var  = t2 / cnt - mean*mean;
        g_stats[bh] = make_float2((float)mean, (float)(1.0/sqrt(var + 1e-5)));
    }
    float* so = state_out ? state_out : g_state_scratch;
    #pragma unroll
    for (int j=0;j<32;j++)
        so[(size_t)bh*4096 + (size_t)row*64 + koff + j] = c*S[j];
}

// ---------------- last_x = x[:, -1, :] -----------------------------------------
__global__ void lastx_kernel(const float* __restrict__ x, float* __restrict__ outp)
{
    const int i = blockIdx.x*blockDim.x + threadIdx.x;
    if (i >= BBAT*CDIM) return;
    const int b  = i >> 10;
    const int cc = i & (CDIM-1);
    outp[i] = x[((size_t)b*TSEQ + (TSEQ-1))*CDIM + cc];
}

// ---------------- launch ---------------------------------------------------------
extern "C" void kernel_launch(void* const* d_in, const int* in_sizes, int n_in,
                              void* d_out, int out_size)
{
    const float* x    = (const float*)d_in[0];
    const float* W_r  = (const float*)d_in[1];
    const float* b_r  = (const float*)d_in[2];
    const float* W_k  = (const float*)d_in[3];
    const float* b_k  = (const float*)d_in[4];
    const float* W_v  = (const float*)d_in[5];
    const float* b_v  = (const float*)d_in[6];
    const float* W_g  = (const float*)d_in[7];
    const float* b_g  = (const float*)d_in[8];
    const float* W_o  = (const float*)d_in[9];
    const float* b_o  = (const float*)d_in[10];
    const float* decay= (const float*)d_in[11];
    const float* eta  = (const float*)d_in[12];
    const float* mixr = (const float*)d_in[13];
    const float* mixk = (const float*)d_in[14];
    const float* mixv = (const float*)d_in[15];
    const float* mixg = (const float*)d_in[16];
    const float* gnw  = (const float*)d_in[17];
    const float* gnb  = (const float*)d_in[18];
    float* out = (float*)d_out;

    const int MAIN  = MROWS*CDIM;
    const int STATE = BBAT*HHEAD*64*64;
    const int LASTX = BBAT*CDIM;
    const bool full = out_size >= MAIN + STATE + LASTX;

    // fused r/k/v/g projections (z picks the projection)
    mma_gemm<0><<<dim3(8,128,4),128>>>(x, W_r,W_k,W_v,W_g, b_r,b_k,b_v,b_g,
                                       mixr,mixk,mixv,mixg, nullptr,nullptr, nullptr);
    l2norm_kernel<<<dim3(32768,2),256>>>();
    scan_kernel<<<128,128>>>(decay, eta, full ? (out + MAIN) : nullptr);
    // output projection with fused groupnorm (A side) and *g (epilogue)
    mma_gemm<1><<<dim3(8,128,1),128>>>(nullptr, W_o,nullptr,nullptr,nullptr,
                                       b_o,nullptr,nullptr,nullptr,
                                       nullptr,nullptr,nullptr,nullptr,
                                       gnw, gnb, out);
    if (full) lastx_kernel<<<32,256>>>(x, out + MAIN + STATE);
}

// round 5
// speedup vs baseline: 1.2341x; 1.2341x over previous
#include <cuda_runtime.h>
#include <cstdint>

#define MROWS 16384
#define CDIM  1024
#define TSEQ  2048
#define BBAT  8
#define HHEAD 16

// ---------------- scratch (static __device__ allocations only) ----------------
__device__ float g_r  [(size_t)MROWS*CDIM];
__device__ float g_k  [(size_t)MROWS*CDIM];
__device__ float g_v  [(size_t)MROWS*CDIM];
__device__ float g_g  [(size_t)MROWS*CDIM];
__device__ float g_wkv[(size_t)MROWS*CDIM];
__device__ float2 g_stats[BBAT*HHEAD];
__device__ float g_state_scratch[BBAT*HHEAD*64*64];

__device__ __forceinline__ float sigf(float x){ return 1.0f/(1.0f+__expf(-x)); }

__device__ __forceinline__ void split_tf32(float a, uint32_t& hi, uint32_t& lo){
    uint32_t h;
    asm("cvt.rna.tf32.f32 %0, %1;" : "=r"(h) : "f"(a));
    hi = h;
    lo = __float_as_uint(a - __uint_as_float(h));
}

__device__ __forceinline__ void mma_tf32(float* c, const uint32_t* a, const uint32_t* b){
    asm volatile("mma.sync.aligned.m16n8k8.row.col.f32.tf32.tf32.f32 "
        "{%0,%1,%2,%3}, {%4,%5,%6,%7}, {%8,%9}, {%0,%1,%2,%3};"
        : "+f"(c[0]), "+f"(c[1]), "+f"(c[2]), "+f"(c[3])
        : "r"(a[0]), "r"(a[1]), "r"(a[2]), "r"(a[3]), "r"(b[0]), "r"(b[1]));
}

// =====================================================================
// tf32 split GEMM (R2-proven internals: float smem, split in consumer).
// AMODE 0: fused 4-projection launch, z = blockIdx.z:
//   z=0: r = sigmoid(.)          [tf32x2]
//   z=1: k, L2-normalized/head   [tf32x3]
//   z=2: v, L2-normalized/head   [tf32x3]
//   z=3: g = silu(.)             [tf32x2]
//   A = x*mix + x_shift*(1-mix)  (token-shift fused)
// AMODE 1: A = groupnorm(g_wkv), epilogue *g_g -> out   [tf32x3]
// Block 128x128, 4 warps (2x2 of 64x64), BK=16, double-buffered.
// =====================================================================
template<int AMODE>
__global__ __launch_bounds__(128, 2)
void mma_gemm(const float* __restrict__ x,
              const float* __restrict__ W0, const float* __restrict__ W1,
              const float* __restrict__ W2, const float* __restrict__ W3,
              const float* __restrict__ b0p, const float* __restrict__ b1p,
              const float* __restrict__ b2p, const float* __restrict__ b3p,
              const float* __restrict__ m0p, const float* __restrict__ m1p,
              const float* __restrict__ m2p, const float* __restrict__ m3p,
              const float* __restrict__ gnw, const float* __restrict__ gnb,
              float* __restrict__ out_ext)
{
    __shared__ float As[2][16][132];   // [k][m] transposed
    __shared__ float Bs[2][16][132];   // [k][n] transposed

    const int z = (AMODE==0) ? blockIdx.z : -1;
    const float* W    = (AMODE==0) ? (z==0?W0:z==1?W1:z==2?W2:W3) : W0;
    const float* bias = (AMODE==0) ? (z==0?b0p:z==1?b1p:z==2?b2p:b3p) : b0p;
    const float* mix  = (AMODE==0) ? (z==0?m0p:z==1?m1p:z==2?m2p:m3p) : nullptr;
    float* out        = (AMODE==0) ? (z==0?g_r:z==1?g_k:z==2?g_v:g_g) : out_ext;
    const bool pass3  = (AMODE==1) || z==1 || z==2;   // tf32x3 for k, v, out

    const int tid  = threadIdx.x;
    const int lane = tid & 31;
    const int warp = tid >> 5;
    const int warpM = warp >> 1, warpN = warp & 1;
    const int bm = blockIdx.y, bn = blockIdx.x;

    const int lm  = tid >> 2;         // 0..31
    const int lk4 = (tid & 3) * 4;    // 0,4,8,12

    float c[4][8][4];
    #pragma unroll
    for (int i=0;i<4;i++)
        #pragma unroll
        for (int j=0;j<8;j++)
            #pragma unroll
            for (int q=0;q<4;q++) c[i][j][q]=0.f;

    float4 pa[4], pb[4];

    auto load_stage = [&](int kt){
        const int koff = kt*16 + lk4;
        #pragma unroll
        for (int i=0;i<4;i++){
            const int gm = bm*128 + lm + 32*i;
            if (AMODE==0){
                float4 xa = *(const float4*)(x + (size_t)gm*CDIM + koff);
                float4 mv = *(const float4*)(mix + koff);
                float4 xs = make_float4(0,0,0,0);
                if ((gm & (TSEQ-1)) != 0)
                    xs = *(const float4*)(x + (size_t)(gm-1)*CDIM + koff);
                pa[i].x = xa.x*mv.x + xs.x*(1.0f-mv.x);
                pa[i].y = xa.y*mv.y + xs.y*(1.0f-mv.y);
                pa[i].z = xa.z*mv.z + xs.z*(1.0f-mv.z);
                pa[i].w = xa.w*mv.w + xs.w*(1.0f-mv.w);
            } else {
                float4 w  = *(const float4*)(g_wkv + (size_t)gm*CDIM + koff);
                const int bh = (gm >> 11)*HHEAD + (koff >> 6);
                const float2 st = g_stats[bh];
                float4 gw = *(const float4*)(gnw + koff);
                float4 gb = *(const float4*)(gnb + koff);
                pa[i].x = (w.x - st.x)*st.y*gw.x + gb.x;
                pa[i].y = (w.y - st.x)*st.y*gw.y + gb.y;
                pa[i].z = (w.z - st.x)*st.y*gw.z + gb.z;
                pa[i].w = (w.w - st.x)*st.y*gw.w + gb.w;
            }
            const int gn = bn*128 + lm + 32*i;
            pb[i] = *(const float4*)(W + (size_t)gn*CDIM + koff);
        }
    };
    auto store_stage = [&](int buf){
        #pragma unroll
        for (int i=0;i<4;i++){
            const int m = lm + 32*i;
            As[buf][lk4+0][m]=pa[i].x; As[buf][lk4+1][m]=pa[i].y;
            As[buf][lk4+2][m]=pa[i].z; As[buf][lk4+3][m]=pa[i].w;
            Bs[buf][lk4+0][m]=pb[i].x; Bs[buf][lk4+1][m]=pb[i].y;
            Bs[buf][lk4+2][m]=pb[i].z; Bs[buf][lk4+3][m]=pb[i].w;
        }
    };

    load_stage(0);

    const int g4 = lane >> 2;
    const int t4 = lane & 3;

    for (int kt=0; kt<CDIM/16; kt++){
        const int buf = kt & 1;
        store_stage(buf);
        __syncthreads();
        if (kt+1 < CDIM/16) load_stage(kt+1);

        #pragma unroll
        for (int ks=0; ks<2; ks++){
            const int kc = ks*8 + t4;
            uint32_t ah[4][4], al[4][4];
            #pragma unroll
            for (int mt=0; mt<4; mt++){
                const int m = warpM*64 + mt*16 + g4;
                split_tf32(As[buf][kc  ][m  ], ah[mt][0], al[mt][0]);
                split_tf32(As[buf][kc  ][m+8], ah[mt][1], al[mt][1]);
                split_tf32(As[buf][kc+4][m  ], ah[mt][2], al[mt][2]);
                split_tf32(As[buf][kc+4][m+8], ah[mt][3], al[mt][3]);
            }
            uint32_t bh_[8][2], bl_[8][2];
            #pragma unroll
            for (int nt=0; nt<8; nt++){
                const int n = warpN*64 + nt*8 + g4;
                split_tf32(Bs[buf][kc  ][n], bh_[nt][0], bl_[nt][0]);
                split_tf32(Bs[buf][kc+4][n], bh_[nt][1], bl_[nt][1]);
            }
            if (pass3){
                #pragma unroll
                for (int mt=0; mt<4; mt++)
                    #pragma unroll
                    for (int nt=0; nt<8; nt++){
                        mma_tf32(c[mt][nt], ah[mt], bh_[nt]);
                        mma_tf32(c[mt][nt], ah[mt], bl_[nt]);
                        mma_tf32(c[mt][nt], al[mt], bh_[nt]);
                    }
            } else {
                #pragma unroll
                for (int mt=0; mt<4; mt++)
                    #pragma unroll
                    for (int nt=0; nt<8; nt++){
                        mma_tf32(c[mt][nt], ah[mt], bh_[nt]);
                        mma_tf32(c[mt][nt], ah[mt], bl_[nt]);
                    }
            }
        }
        __syncthreads();
    }

    // ---- epilogue ----
    const bool donorm = (AMODE==0) && (z==1 || z==2);   // k / v: per-head L2 norm
    #pragma unroll
    for (int mt=0; mt<4; mt++){
        const int r0 = bm*128 + warpM*64 + mt*16 + g4;
        const int r1 = r0 + 8;
        // add bias in place
        #pragma unroll
        for (int nt=0; nt<8; nt++){
            const int col = bn*128 + warpN*64 + nt*8 + t4*2;
            const float2 bb = *(const float2*)(bias + col);
            c[mt][nt][0] += bb.x; c[mt][nt][1] += bb.y;
            c[mt][nt][2] += bb.x; c[mt][nt][3] += bb.y;
        }
        float sc0 = 1.0f, sc1 = 1.0f;
        if (donorm){
            float ss0=0.f, ss1=0.f;
            #pragma unroll
            for (int nt=0; nt<8; nt++){
                ss0 = fmaf(c[mt][nt][0],c[mt][nt][0], fmaf(c[mt][nt][1],c[mt][nt][1], ss0));
                ss1 = fmaf(c[mt][nt][2],c[mt][nt][2], fmaf(c[mt][nt][3],c[mt][nt][3], ss1));
            }
            ss0 += __shfl_xor_sync(0xffffffffu, ss0, 1);
            ss0 += __shfl_xor_sync(0xffffffffu, ss0, 2);
            ss1 += __shfl_xor_sync(0xffffffffu, ss1, 1);
            ss1 += __shfl_xor_sync(0xffffffffu, ss1, 2);
            sc0 = 1.0f/fmaxf(sqrtf(ss0), 1e-12f);
            sc1 = 1.0f/fmaxf(sqrtf(ss1), 1e-12f);
        }
        #pragma unroll
        for (int nt=0; nt<8; nt++){
            const int col = bn*128 + warpN*64 + nt*8 + t4*2;
            float v0 = c[mt][nt][0], v1 = c[mt][nt][1];
            float v2 = c[mt][nt][2], v3 = c[mt][nt][3];
            if (AMODE==0){
                if (z==0){ v0=sigf(v0); v1=sigf(v1); v2=sigf(v2); v3=sigf(v3); }
                else if (z==3){ v0*=sigf(v0); v1*=sigf(v1); v2*=sigf(v2); v3*=sigf(v3); }
                else { v0*=sc0; v1*=sc0; v2*=sc1; v3*=sc1; }
            } else {
                float2 g0 = *(const float2*)(g_g + (size_t)r0*CDIM + col);
                float2 g1 = *(const float2*)(g_g + (size_t)r1*CDIM + col);
                v0*=g0.x; v1*=g0.y; v2*=g1.x; v3*=g1.y;
            }
            *(float2*)(out + (size_t)r0*CDIM + col) = make_float2(v0,v1);
            *(float2*)(out + (size_t)r1*CDIM + col) = make_float2(v2,v3);
        }
    }
}

// ---------------- sequential delta-rule scan: 1 CTA (128 thr) per (b,h) --------
// Thread t owns half a state row. Deferred scalar c (S_actual = c*S).
// Incremental Frobenius norm: ||S - coef*k||^2 = ||S||^2 - 2*coef*q + coef^2
// (k is unit-norm). Exact recompute every 32 steps at the refold.
// Double-buffered smem staging, ONE __syncthreads per step.
__global__ __launch_bounds__(128)
void scan_kernel(const float* __restrict__ decay, const float* __restrict__ eta,
                 float* __restrict__ state_out)
{
    const int bh = blockIdx.x;
    const int b = bh >> 4, h = bh & 15;
    const int t_ = threadIdx.x;
    const int row = t_ >> 1, half = t_ & 1;
    const int lane = t_ & 31, wid = t_ >> 5;
    const int koff = half*32;
    __shared__ __align__(16) float sk[2][64], sr[2][64], sv[2][64];
    __shared__ float red[2][4];
    __shared__ double redd[4][2];

    float S[32];
    #pragma unroll
    for (int j=0;j<32;j++) S[j]=0.f;
    float c = 1.0f;
    float ns = 0.f;                       // ||S_stored||^2 (incremental)
    const float dec = 1.0f/(1.0f+expf(-decay[h]));
    const float et  = 1.0f/(1.0f+expf(-eta[h]));
    const float maxn = 16.0f;
    double wsum = 0.0, wsq = 0.0;

    const size_t base = (size_t)b*TSEQ*CDIM + (size_t)h*64;
    const float* kp = g_k + base;
    const float* rp = g_r + base;
    const float* vp = g_v + base;
    float*       op = g_wkv + base;

    // stage t=0 into buffer 0; prefetch t=1 into regs
    if (t_ < 64){ sk[0][t_] = kp[t_]; sv[0][t_] = vp[t_]; }
    else        { sr[0][t_-64] = rp[t_-64]; }
    float nk=0.f, nr=0.f, nv=0.f;
    if (t_ < 64){ nk = kp[CDIM+t_]; nv = vp[CDIM+t_]; }
    else        { nr = rp[CDIM+t_-64]; }
    __syncthreads();

    for (int t=0; t<TSEQ; t++){
        const int buf  = t & 1;
        const int nbuf = buf ^ 1;
        // stage t+1 into nbuf; start t+2 loads (earliest possible)
        if (t+1 < TSEQ){
            if (t_ < 64){ sk[nbuf][t_]=nk; sv[nbuf][t_]=nv; }
            else        { sr[nbuf][t_-64]=nr; }
        }
        if (t+2 < TSEQ){
            if (t_ < 64){ nk = kp[2*CDIM+t_]; nv = vp[2*CDIM+t_]; }
            else        { nr = rp[2*CDIM+t_-64]; }
        }
        // ---- compute on buf ----
        const float4* k4 = (const float4*)(&sk[buf][koff]);
        float q0=0,q1=0,q2=0,q3=0;
        #pragma unroll
        for (int j=0;j<8;j++){
            float4 kv = k4[j];
            q0 = fmaf(S[4*j+0], kv.x, q0);
            q1 = fmaf(S[4*j+1], kv.y, q1);
            q2 = fmaf(S[4*j+2], kv.z, q2);
            q3 = fmaf(S[4*j+3], kv.w, q3);
        }
        float qp = (q0+q1)+(q2+q3);
        qp += __shfl_xor_sync(0xffffffffu, qp, 1);    // full-row dot
        const float vi   = sv[buf][row];
        const float err  = c*qp - vi;
        const float c1   = dec*c;
        const float coef = (et*err)/c1;
        const bool exact = ((t & 31) == 31);
        // update half-row
        #pragma unroll
        for (int j=0;j<8;j++){
            float4 kv = k4[j];
            S[4*j+0] = fmaf(-coef, kv.x, S[4*j+0]);
            S[4*j+1] = fmaf(-coef, kv.y, S[4*j+1]);
            S[4*j+2] = fmaf(-coef, kv.z, S[4*j+2]);
            S[4*j+3] = fmaf(-coef, kv.w, S[4*j+3]);
        }
        // norm-delta (or exact recompute every 32 steps)
        float val;
        if (exact){
            float u0=0,u1=0,u2=0,u3=0;
            #pragma unroll
            for (int j=0;j<8;j++){
                u0 = fmaf(S[4*j+0],S[4*j+0],u0);
                u1 = fmaf(S[4*j+1],S[4*j+1],u1);
                u2 = fmaf(S[4*j+2],S[4*j+2],u2);
                u3 = fmaf(S[4*j+3],S[4*j+3],u3);
            }
            val = (u0+u1)+(u2+u3);
        } else {
            val = 0.5f*fmaf(coef, coef, -2.0f*coef*qp);
        }
        // readout dot (overlaps the reduction tree below)
        const float4* r4 = (const float4*)(&sr[buf][koff]);
        float w0=0,w1=0,w2=0,w3=0;
        #pragma unroll
        for (int j=0;j<8;j++){
            float4 rv = r4[j];
            w0 = fmaf(S[4*j+0], rv.x, w0);
            w1 = fmaf(S[4*j+1], rv.y, w1);
            w2 = fmaf(S[4*j+2], rv.z, w2);
            w3 = fmaf(S[4*j+3], rv.w, w3);
        }
        #pragma unroll
        for (int o=16;o;o>>=1) val += __shfl_xor_sync(0xffffffffu, val, o);
        if (lane==0) red[buf][wid]=val;
        float wpart = (w0+w1)+(w2+w3);
        wpart += __shfl_xor_sync(0xffffffffu, wpart, 1);
        __syncthreads();
        // ---- post-sync ----
        const float tot = red[buf][0]+red[buf][1]+red[buf][2]+red[buf][3];
        ns = exact ? tot : fmaxf(ns + tot, 0.f);
        const float nrm = c1*sqrtf(ns);
        c = (nrm > maxn) ? c1*(maxn/nrm) : c1;
        const float wv = c*wpart;
        if (half==0) op[row] = wv;
        wsum += (double)wv;               // both halves accumulate -> /2 later
        wsq  += (double)wv*(double)wv;
        if (exact){
            #pragma unroll
            for (int j=0;j<32;j++) S[j]*=c;
            ns *= c*c;
            c = 1.0f;
        }
        kp += CDIM; rp += CDIM; vp += CDIM; op += CDIM;
    }
    // group-norm stats over (T, D) for this (b,h)
    double a1=wsum, a2=wsq;
    #pragma unroll
    for (int o=16;o;o>>=1){
        a1 += __shfl_xor_sync(0xffffffffu, a1, o);
        a2 += __shfl_xor_sync(0xffffffffu, a2, o);
    }
    if (lane==0){ redd[wid][0]=a1; redd[wid][1]=a2; }
    __syncthreads();
    if (t_==0){
        const double t1 = redd[0][0]+redd[1][0]+redd[2][0]+redd[3][0];
        const double t2 = redd[0][1]+redd[1][1]+redd[2][1]+redd[3][1];
        const double cnt = 2.0*(double)TSEQ*64.0;
        const double mean = t1 / cnt;
        const double var  = t2 / cnt - mean*mean;
        g_stats[bh] = make_float2((float)mean, (float)(1.0/sqrt(var + 1e-5)));
    }
    float* so = state_out ? state_out : g_state_scratch;
    #pragma unroll
    for (int j=0;j<32;j++)
        so[(size_t)bh*4096 + (size_t)row*64 + koff + j] = c*S[j];
}

// ---------------- last_x = x[:, -1, :] -----------------------------------------
__global__ void lastx_kernel(const float* __restrict__ x, float* __restrict__ outp)
{
    const int i = blockIdx.x*blockDim.x + threadIdx.x;
    if (i >= BBAT*CDIM) return;
    const int b  = i >> 10;
    const int cc = i & (CDIM-1);
    outp[i] = x[((size_t)b*TSEQ + (TSEQ-1))*CDIM + cc];
}

// ---------------- launch ---------------------------------------------------------
extern "C" void kernel_launch(void* const* d_in, const int* in_sizes, int n_in,
                              void* d_out, int out_size)
{
    const float* x    = (const float*)d_in[0];
    const float* W_r  = (const float*)d_in[1];
    const float* b_r  = (const float*)d_in[2];
    const float* W_k  = (const float*)d_in[3];
    const float* b_k  = (const float*)d_in[4];
    const float* W_v  = (const float*)d_in[5];
    const float* b_v  = (const float*)d_in[6];
    const float* W_g  = (const float*)d_in[7];
    const float* b_g  = (const float*)d_in[8];
    const float* W_o  = (const float*)d_in[9];
    const float* b_o  = (const float*)d_in[10];
    const float* decay= (const float*)d_in[11];
    const float* eta  = (const float*)d_in[12];
    const float* mixr = (const float*)d_in[13];
    const float* mixk = (const float*)d_in[14];
    const float* mixv = (const float*)d_in[15];
    const float* mixg = (const float*)d_in[16];
    const float* gnw  = (const float*)d_in[17];
    const float* gnb  = (const float*)d_in[18];
    float* out = (float*)d_out;

    const int MAIN  = MROWS*CDIM;
    const int STATE = BBAT*HHEAD*64*64;
    const int LASTX = BBAT*CDIM;
    const bool full = out_size >= MAIN + STATE + LASTX;

    // fused r/k/v/g projections (z picks projection; k/v L2-norm fused in epilogue)
    mma_gemm<0><<<dim3(8,128,4),128>>>(x, W_r,W_k,W_v,W_g, b_r,b_k,b_v,b_g,
                                       mixr,mixk,mixv,mixg, nullptr,nullptr, nullptr);
    scan_kernel<<<128,128>>>(decay, eta, full ? (out + MAIN) : nullptr);
    // output projection with fused groupnorm (A side) and *g (epilogue)
    mma_gemm<1><<<dim3(8,128,1),128>>>(nullptr, W_o,nullptr,nullptr,nullptr,
                                       b_o,nullptr,nullptr,nullptr,
                                       nullptr,nullptr,nullptr,nullptr,
                                       gnw, gnb, out);
    if (full) lastx_kernel<<<32,256>>>(x, out + MAIN + STATE);
}

// round 6
// speedup vs baseline: 1.5286x; 1.2386x over previous
#include <cuda_runtime.h>
#include <cstdint>

#define MROWS 16384
#define CDIM  1024
#define TSEQ  2048
#define BBAT  8
#define HHEAD 16

// ---------------- scratch (static __device__ allocations only) ----------------
__device__ float g_r  [(size_t)MROWS*CDIM];
__device__ float g_k  [(size_t)MROWS*CDIM];
__device__ float g_v  [(size_t)MROWS*CDIM];
__device__ float g_g  [(size_t)MROWS*CDIM];
__device__ float g_wkv[(size_t)MROWS*CDIM];
__device__ float2 g_stats[BBAT*HHEAD];
__device__ float g_state_scratch[BBAT*HHEAD*64*64];

enum { EPI_NONE=0, EPI_SIG=1, EPI_SILU=2, EPI_GOUT=3 };

__device__ __forceinline__ float sigf(float x){ return 1.0f/(1.0f+__expf(-x)); }

__device__ __forceinline__ void split_tf32(float a, uint32_t& hi, uint32_t& lo){
    uint32_t h;
    asm("cvt.rna.tf32.f32 %0, %1;" : "=r"(h) : "f"(a));
    hi = h;
    lo = __float_as_uint(a - __uint_as_float(h));
}

__device__ __forceinline__ void mma_tf32(float* c, const uint32_t* a, const uint32_t* b){
    asm volatile("mma.sync.aligned.m16n8k8.row.col.f32.tf32.tf32.f32 "
        "{%0,%1,%2,%3}, {%4,%5,%6,%7}, {%8,%9}, {%0,%1,%2,%3};"
        : "+f"(c[0]), "+f"(c[1]), "+f"(c[2]), "+f"(c[3])
        : "r"(a[0]), "r"(a[1]), "r"(a[2]), "r"(a[3]), "r"(b[0]), "r"(b[1]));
}

// =====================================================================
// tf32 split GEMM core (R2-proven internals: float smem, split in consumer).
// AMODE 0: A = x*mix + x_shift*(1-mix)   (token-shift fused)
// AMODE 1: A = groupnorm(g_wkv) (stats from scan), epilogue EPI_GOUT *g_g.
// PASS3: tf32x3 (k, v) vs tf32x2 (r, g, out).
// DONORM: per-head L2 normalization fused in epilogue (k, v).
// Block 128x128, 4 warps (2x2 of 64x64), BK=16, double-buffered.
// Shared memory passed in by reference (shared across instantiations).
// =====================================================================
template<int AMODE, bool PASS3, int EPI, bool DONORM>
__device__ __forceinline__ void gemm_core(
    float (&As)[2][16][132], float (&Bs)[2][16][132],
    int bm, int bn,
    const float* __restrict__ x,  const float* __restrict__ W,
    const float* __restrict__ bias, const float* __restrict__ mix,
    const float* __restrict__ gnw, const float* __restrict__ gnb,
    float* __restrict__ out)
{
    const int tid  = threadIdx.x;
    const int lane = tid & 31;
    const int warp = tid >> 5;
    const int warpM = warp >> 1, warpN = warp & 1;

    const int lm  = tid >> 2;         // 0..31
    const int lk4 = (tid & 3) * 4;    // 0,4,8,12

    float c[4][8][4];
    #pragma unroll
    for (int i=0;i<4;i++)
        #pragma unroll
        for (int j=0;j<8;j++)
            #pragma unroll
            for (int q=0;q<4;q++) c[i][j][q]=0.f;

    float4 pa[4], pb[4];

    auto load_stage = [&](int kt){
        const int koff = kt*16 + lk4;
        #pragma unroll
        for (int i=0;i<4;i++){
            const int gm = bm*128 + lm + 32*i;
            if (AMODE==0){
                float4 xa = *(const float4*)(x + (size_t)gm*CDIM + koff);
                float4 mv = *(const float4*)(mix + koff);
                float4 xs = make_float4(0,0,0,0);
                if ((gm & (TSEQ-1)) != 0)
                    xs = *(const float4*)(x + (size_t)(gm-1)*CDIM + koff);
                pa[i].x = xa.x*mv.x + xs.x*(1.0f-mv.x);
                pa[i].y = xa.y*mv.y + xs.y*(1.0f-mv.y);
                pa[i].z = xa.z*mv.z + xs.z*(1.0f-mv.z);
                pa[i].w = xa.w*mv.w + xs.w*(1.0f-mv.w);
            } else {
                float4 w  = *(const float4*)(g_wkv + (size_t)gm*CDIM + koff);
                const int bh = (gm >> 11)*HHEAD + (koff >> 6);
                const float2 st = g_stats[bh];
                float4 gw = *(const float4*)(gnw + koff);
                float4 gb = *(const float4*)(gnb + koff);
                pa[i].x = (w.x - st.x)*st.y*gw.x + gb.x;
                pa[i].y = (w.y - st.x)*st.y*gw.y + gb.y;
                pa[i].z = (w.z - st.x)*st.y*gw.z + gb.z;
                pa[i].w = (w.w - st.x)*st.y*gw.w + gb.w;
            }
            const int gn = bn*128 + lm + 32*i;
            pb[i] = *(const float4*)(W + (size_t)gn*CDIM + koff);
        }
    };
    auto store_stage = [&](int buf){
        #pragma unroll
        for (int i=0;i<4;i++){
            const int m = lm + 32*i;
            As[buf][lk4+0][m]=pa[i].x; As[buf][lk4+1][m]=pa[i].y;
            As[buf][lk4+2][m]=pa[i].z; As[buf][lk4+3][m]=pa[i].w;
            Bs[buf][lk4+0][m]=pb[i].x; Bs[buf][lk4+1][m]=pb[i].y;
            Bs[buf][lk4+2][m]=pb[i].z; Bs[buf][lk4+3][m]=pb[i].w;
        }
    };

    load_stage(0);

    const int g4 = lane >> 2;
    const int t4 = lane & 3;

    for (int kt=0; kt<CDIM/16; kt++){
        const int buf = kt & 1;
        store_stage(buf);
        __syncthreads();
        if (kt+1 < CDIM/16) load_stage(kt+1);

        #pragma unroll
        for (int ks=0; ks<2; ks++){
            const int kc = ks*8 + t4;
            uint32_t ah[4][4], al[4][4];
            #pragma unroll
            for (int mt=0; mt<4; mt++){
                const int m = warpM*64 + mt*16 + g4;
                split_tf32(As[buf][kc  ][m  ], ah[mt][0], al[mt][0]);
                split_tf32(As[buf][kc  ][m+8], ah[mt][1], al[mt][1]);
                split_tf32(As[buf][kc+4][m  ], ah[mt][2], al[mt][2]);
                split_tf32(As[buf][kc+4][m+8], ah[mt][3], al[mt][3]);
            }
            uint32_t bh_[8][2], bl_[8][2];
            #pragma unroll
            for (int nt=0; nt<8; nt++){
                const int n = warpN*64 + nt*8 + g4;
                split_tf32(Bs[buf][kc  ][n], bh_[nt][0], bl_[nt][0]);
                split_tf32(Bs[buf][kc+4][n], bh_[nt][1], bl_[nt][1]);
            }
            #pragma unroll
            for (int mt=0; mt<4; mt++)
                #pragma unroll
                for (int nt=0; nt<8; nt++){
                    mma_tf32(c[mt][nt], ah[mt], bh_[nt]);
                    mma_tf32(c[mt][nt], ah[mt], bl_[nt]);
                    if (PASS3) mma_tf32(c[mt][nt], al[mt], bh_[nt]);
                }
        }
        __syncthreads();
    }

    // ---- epilogue ----
    #pragma unroll
    for (int mt=0; mt<4; mt++){
        const int r0 = bm*128 + warpM*64 + mt*16 + g4;
        const int r1 = r0 + 8;
        #pragma unroll
        for (int nt=0; nt<8; nt++){
            const int col = bn*128 + warpN*64 + nt*8 + t4*2;
            const float2 bb = *(const float2*)(bias + col);
            c[mt][nt][0] += bb.x; c[mt][nt][1] += bb.y;
            c[mt][nt][2] += bb.x; c[mt][nt][3] += bb.y;
        }
        float sc0 = 1.0f, sc1 = 1.0f;
        if (DONORM){
            float ss0=0.f, ss1=0.f;
            #pragma unroll
            for (int nt=0; nt<8; nt++){
                ss0 = fmaf(c[mt][nt][0],c[mt][nt][0], fmaf(c[mt][nt][1],c[mt][nt][1], ss0));
                ss1 = fmaf(c[mt][nt][2],c[mt][nt][2], fmaf(c[mt][nt][3],c[mt][nt][3], ss1));
            }
            ss0 += __shfl_xor_sync(0xffffffffu, ss0, 1);
            ss0 += __shfl_xor_sync(0xffffffffu, ss0, 2);
            ss1 += __shfl_xor_sync(0xffffffffu, ss1, 1);
            ss1 += __shfl_xor_sync(0xffffffffu, ss1, 2);
            sc0 = 1.0f/fmaxf(sqrtf(ss0), 1e-12f);
            sc1 = 1.0f/fmaxf(sqrtf(ss1), 1e-12f);
        }
        #pragma unroll
        for (int nt=0; nt<8; nt++){
            const int col = bn*128 + warpN*64 + nt*8 + t4*2;
            float v0 = c[mt][nt][0], v1 = c[mt][nt][1];
            float v2 = c[mt][nt][2], v3 = c[mt][nt][3];
            if (DONORM){ v0*=sc0; v1*=sc0; v2*=sc1; v3*=sc1; }
            if (EPI==EPI_SIG){ v0=sigf(v0); v1=sigf(v1); v2=sigf(v2); v3=sigf(v3); }
            else if (EPI==EPI_SILU){ v0*=sigf(v0); v1*=sigf(v1); v2*=sigf(v2); v3*=sigf(v3); }
            else if (EPI==EPI_GOUT){
                float2 g0 = *(const float2*)(g_g + (size_t)r0*CDIM + col);
                float2 g1 = *(const float2*)(g_g + (size_t)r1*CDIM + col);
                v0*=g0.x; v1*=g0.y; v2*=g1.x; v3*=g1.y;
            }
            *(float2*)(out + (size_t)r0*CDIM + col) = make_float2(v0,v1);
            *(float2*)(out + (size_t)r1*CDIM + col) = make_float2(v2,v3);
        }
    }
}

// ---------------- scan body: 1 CTA (128 thr) per (b,h) -------------------------
// Thread t owns half a state row. Deferred scalar c (S_actual = c*S).
// Incremental Frobenius norm (k unit-norm); exact recompute every 32 steps.
// Double-buffered smem staging, ONE __syncthreads per step.
__device__ __forceinline__ void scan_body(
    int bh, const float* __restrict__ decay, const float* __restrict__ eta,
    float* __restrict__ state_out)
{
    __shared__ __align__(16) float sk[2][64], sr[2][64], sv[2][64];
    __shared__ float red[2][4];
    __shared__ double redd[4][2];

    const int b = bh >> 4, h = bh & 15;
    const int t_ = threadIdx.x;
    const int row = t_ >> 1, half = t_ & 1;
    const int lane = t_ & 31, wid = t_ >> 5;
    const int koff = half*32;

    float S[32];
    #pragma unroll
    for (int j=0;j<32;j++) S[j]=0.f;
    float c = 1.0f;
    float ns = 0.f;
    const float dec = 1.0f/(1.0f+expf(-decay[h]));
    const float et  = 1.0f/(1.0f+expf(-eta[h]));
    const float maxn = 16.0f;
    double wsum = 0.0, wsq = 0.0;

    const size_t base = (size_t)b*TSEQ*CDIM + (size_t)h*64;
    const float* kp = g_k + base;
    const float* rp = g_r + base;
    const float* vp = g_v + base;
    float*       op = g_wkv + base;

    if (t_ < 64){ sk[0][t_] = kp[t_]; sv[0][t_] = vp[t_]; }
    else        { sr[0][t_-64] = rp[t_-64]; }
    float nk=0.f, nr=0.f, nv=0.f;
    if (t_ < 64){ nk = kp[CDIM+t_]; nv = vp[CDIM+t_]; }
    else        { nr = rp[CDIM+t_-64]; }
    __syncthreads();

    for (int t=0; t<TSEQ; t++){
        const int buf  = t & 1;
        const int nbuf = buf ^ 1;
        if (t+1 < TSEQ){
            if (t_ < 64){ sk[nbuf][t_]=nk; sv[nbuf][t_]=nv; }
            else        { sr[nbuf][t_-64]=nr; }
        }
        if (t+2 < TSEQ){
            if (t_ < 64){ nk = kp[2*CDIM+t_]; nv = vp[2*CDIM+t_]; }
            else        { nr = rp[2*CDIM+t_-64]; }
        }
        const float4* k4 = (const float4*)(&sk[buf][koff]);
        float q0=0,q1=0,q2=0,q3=0;
        #pragma unroll
        for (int j=0;j<8;j++){
            float4 kv = k4[j];
            q0 = fmaf(S[4*j+0], kv.x, q0);
            q1 = fmaf(S[4*j+1], kv.y, q1);
            q2 = fmaf(S[4*j+2], kv.z, q2);
            q3 = fmaf(S[4*j+3], kv.w, q3);
        }
        float qp = (q0+q1)+(q2+q3);
        qp += __shfl_xor_sync(0xffffffffu, qp, 1);
        const float vi   = sv[buf][row];
        const float err  = c*qp - vi;
        const float c1   = dec*c;
        const float coef = (et*err)/c1;
        const bool exact = ((t & 31) == 31);
        #pragma unroll
        for (int j=0;j<8;j++){
            float4 kv = k4[j];
            S[4*j+0] = fmaf(-coef, kv.x, S[4*j+0]);
            S[4*j+1] = fmaf(-coef, kv.y, S[4*j+1]);
            S[4*j+2] = fmaf(-coef, kv.z, S[4*j+2]);
            S[4*j+3] = fmaf(-coef, kv.w, S[4*j+3]);
        }
        float val;
        if (exact){
            float u0=0,u1=0,u2=0,u3=0;
            #pragma unroll
            for (int j=0;j<8;j++){
                u0 = fmaf(S[4*j+0],S[4*j+0],u0);
                u1 = fmaf(S[4*j+1],S[4*j+1],u1);
                u2 = fmaf(S[4*j+2],S[4*j+2],u2);
                u3 = fmaf(S[4*j+3],S[4*j+3],u3);
            }
            val = (u0+u1)+(u2+u3);
        } else {
            val = 0.5f*fmaf(coef, coef, -2.0f*coef*qp);
        }
        const float4* r4 = (const float4*)(&sr[buf][koff]);
        float w0=0,w1=0,w2=0,w3=0;
        #pragma unroll
        for (int j=0;j<8;j++){
            float4 rv = r4[j];
            w0 = fmaf(S[4*j+0], rv.x, w0);
            w1 = fmaf(S[4*j+1], rv.y, w1);
            w2 = fmaf(S[4*j+2], rv.z, w2);
            w3 = fmaf(S[4*j+3], rv.w, w3);
        }
        #pragma unroll
        for (int o=16;o;o>>=1) val += __shfl_xor_sync(0xffffffffu, val, o);
        if (lane==0) red[buf][wid]=val;
        float wpart = (w0+w1)+(w2+w3);
        wpart += __shfl_xor_sync(0xffffffffu, wpart, 1);
        __syncthreads();
        const float tot = red[buf][0]+red[buf][1]+red[buf][2]+red[buf][3];
        ns = exact ? tot : fmaxf(ns + tot, 0.f);
        const float nrm = c1*sqrtf(ns);
        c = (nrm > maxn) ? c1*(maxn/nrm) : c1;
        const float wv = c*wpart;
        if (half==0) op[row] = wv;
        wsum += (double)wv;
        wsq  += (double)wv*(double)wv;
        if (exact){
            #pragma unroll
            for (int j=0;j<32;j++) S[j]*=c;
            ns *= c*c;
            c = 1.0f;
        }
        kp += CDIM; rp += CDIM; vp += CDIM; op += CDIM;
    }
    double a1=wsum, a2=wsq;
    #pragma unroll
    for (int o=16;o;o>>=1){
        a1 += __shfl_xor_sync(0xffffffffu, a1, o);
        a2 += __shfl_xor_sync(0xffffffffu, a2, o);
    }
    if (lane==0){ redd[wid][0]=a1; redd[wid][1]=a2; }
    __syncthreads();
    if (t_==0){
        const double t1 = redd[0][0]+redd[1][0]+redd[2][0]+redd[3][0];
        const double t2 = redd[0][1]+redd[1][1]+redd[2][1]+redd[3][1];
        const double cnt = 2.0*(double)TSEQ*64.0;
        const double mean = t1 / cnt;
        const double var  = t2 / cnt - mean*mean;
        g_stats[bh] = make_float2((float)mean, (float)(1.0/sqrt(var + 1e-5)));
    }
    float* so = state_out ? state_out : g_state_scratch;
    #pragma unroll
    for (int j=0;j<32;j++)
        so[(size_t)bh*4096 + (size_t)row*64 + koff + j] = c*S[j];
}

// ---------------- kernels ------------------------------------------------------

// r/k/v projections (z picks projection)
__global__ __launch_bounds__(128, 2)
void proj_kernel(const float* __restrict__ x,
                 const float* __restrict__ W_r, const float* __restrict__ W_k,
                 const float* __restrict__ W_v,
                 const float* __restrict__ b_r, const float* __restrict__ b_k,
                 const float* __restrict__ b_v,
                 const float* __restrict__ mr, const float* __restrict__ mk,
                 const float* __restrict__ mv)
{
    __shared__ float As[2][16][132];
    __shared__ float Bs[2][16][132];
    const int bm = blockIdx.y, bn = blockIdx.x, z = blockIdx.z;
    if (z==0)
        gemm_core<0,false,EPI_SIG, false>(As,Bs,bm,bn, x, W_r, b_r, mr, nullptr,nullptr, g_r);
    else if (z==1)
        gemm_core<0,true, EPI_NONE,true >(As,Bs,bm,bn, x, W_k, b_k, mk, nullptr,nullptr, g_k);
    else
        gemm_core<0,true, EPI_NONE,true >(As,Bs,bm,bn, x, W_v, b_v, mv, nullptr,nullptr, g_v);
}

// merged: scan (CTAs 0..127) + g projection (CTAs 128..1151)
__global__ __launch_bounds__(128, 2)
void scan_g_kernel(const float* __restrict__ x,
                   const float* __restrict__ W_g, const float* __restrict__ b_g,
                   const float* __restrict__ mg,
                   const float* __restrict__ decay, const float* __restrict__ eta,
                   float* __restrict__ state_out)
{
    __shared__ float As[2][16][132];
    __shared__ float Bs[2][16][132];
    if (blockIdx.x < 128){
        scan_body(blockIdx.x, decay, eta, state_out);
    } else {
        const int bi = blockIdx.x - 128;
        gemm_core<0,false,EPI_SILU,false>(As,Bs, bi>>3, bi&7, x, W_g, b_g, mg,
                                          nullptr,nullptr, g_g);
    }
}

// output projection: groupnorm fused into A-loader, *g in epilogue, tf32x2
__global__ __launch_bounds__(128, 2)
void outproj_kernel(const float* __restrict__ W_o, const float* __restrict__ b_o,
                    const float* __restrict__ gnw, const float* __restrict__ gnb,
                    float* __restrict__ out)
{
    __shared__ float As[2][16][132];
    __shared__ float Bs[2][16][132];
    gemm_core<1,false,EPI_GOUT,false>(As,Bs, blockIdx.y, blockIdx.x,
                                      nullptr, W_o, b_o, nullptr, gnw, gnb, out);
}

// last_x = x[:, -1, :]
__global__ void lastx_kernel(const float* __restrict__ x, float* __restrict__ outp)
{
    const int i = blockIdx.x*blockDim.x + threadIdx.x;
    if (i >= BBAT*CDIM) return;
    const int b  = i >> 10;
    const int cc = i & (CDIM-1);
    outp[i] = x[((size_t)b*TSEQ + (TSEQ-1))*CDIM + cc];
}

// ---------------- launch --------------------------------------------------------
extern "C" void kernel_launch(void* const* d_in, const int* in_sizes, int n_in,
                              void* d_out, int out_size)
{
    const float* x    = (const float*)d_in[0];
    const float* W_r  = (const float*)d_in[1];
    const float* b_r  = (const float*)d_in[2];
    const float* W_k  = (const float*)d_in[3];
    const float* b_k  = (const float*)d_in[4];
    const float* W_v  = (const float*)d_in[5];
    const float* b_v  = (const float*)d_in[6];
    const float* W_g  = (const float*)d_in[7];
    const float* b_g  = (const float*)d_in[8];
    const float* W_o  = (const float*)d_in[9];
    const float* b_o  = (const float*)d_in[10];
    const float* decay= (const float*)d_in[11];
    const float* eta  = (const float*)d_in[12];
    const float* mixr = (const float*)d_in[13];
    const float* mixk = (const float*)d_in[14];
    const float* mixv = (const float*)d_in[15];
    const float* mixg = (const float*)d_in[16];
    const float* gnw  = (const float*)d_in[17];
    const float* gnb  = (const float*)d_in[18];
    float* out = (float*)d_out;

    const int MAIN  = MROWS*CDIM;
    const int STATE = BBAT*HHEAD*64*64;
    const int LASTX = BBAT*CDIM;
    const bool full = out_size >= MAIN + STATE + LASTX;

    proj_kernel<<<dim3(8,128,3),128>>>(x, W_r,W_k,W_v, b_r,b_k,b_v, mixr,mixk,mixv);
    scan_g_kernel<<<128+1024,128>>>(x, W_g, b_g, mixg, decay, eta,
                                    full ? (out + MAIN) : nullptr);
    outproj_kernel<<<dim3(8,128),128>>>(W_o, b_o, gnw, gnb, out);
    if (full) lastx_kernel<<<32,256>>>(x, out + MAIN + STATE);
}

// round 7
// speedup vs baseline: 1.8343x; 1.2000x over previous
#include <cuda_runtime.h>
#include <cstdint>

#define MROWS 16384
#define CDIM  1024
#define TSEQ  2048
#define BBAT  8
#define HHEAD 16
#define SST   136   // smem row stride (words): 136 mod 32 = 8 -> conflict-free frags

// ---------------- scratch (static __device__ allocations only) ----------------
__device__ float g_r  [(size_t)MROWS*CDIM];
__device__ float g_k  [(size_t)MROWS*CDIM];
__device__ float g_v  [(size_t)MROWS*CDIM];
__device__ float g_g  [(size_t)MROWS*CDIM];
__device__ float g_wkv[(size_t)MROWS*CDIM];
__device__ float2 g_stats[BBAT*HHEAD];
__device__ float g_state_scratch[BBAT*HHEAD*64*64];

enum { EPI_NONE=0, EPI_SIG=1, EPI_SILU=2, EPI_GOUT=3 };

__device__ __forceinline__ float sigf(float x){ return 1.0f/(1.0f+__expf(-x)); }

// pack two floats into bf16x2 (lo -> low half, hi -> high half)
__device__ __forceinline__ uint32_t cvt_bf16x2(float lo, float hi){
    uint32_t r;
    asm("cvt.rn.satfinite.bf16x2.f32 %0, %1, %2;" : "=r"(r) : "f"(hi), "f"(lo));
    return r;
}
// double-bf16 split of a pair: a ~= hi + lo with ~16 mantissa bits total
__device__ __forceinline__ void split_pack(float a0, float a1, uint32_t& hp, uint32_t& lp){
    hp = cvt_bf16x2(a0, a1);
    float h0 = __uint_as_float(hp << 16);
    float h1 = __uint_as_float(hp & 0xffff0000u);
    lp = cvt_bf16x2(a0 - h0, a1 - h1);
}

__device__ __forceinline__ void mma_bf16(float* c, const uint32_t* a, const uint32_t* b){
    asm volatile("mma.sync.aligned.m16n8k16.row.col.f32.bf16.bf16.f32 "
        "{%0,%1,%2,%3}, {%4,%5,%6,%7}, {%8,%9}, {%0,%1,%2,%3};"
        : "+f"(c[0]), "+f"(c[1]), "+f"(c[2]), "+f"(c[3])
        : "r"(a[0]), "r"(a[1]), "r"(a[2]), "r"(a[3]), "r"(b[0]), "r"(b[1]));
}

// =====================================================================
// bf16x3 GEMM core: a,b each split hi/lo bf16 in the loader; compute
// ah*bh + ah*bl + al*bh with m16n8k16 bf16 MMAs (error ~1e-5 relative).
// AMODE 0: A = x*mix + x_shift*(1-mix)   (token-shift fused)
// AMODE 1: A = groupnorm(g_wkv) (stats from scan), epilogue EPI_GOUT *g_g.
// DONORM: per-head L2 normalization fused in epilogue (k, v).
// Block 128x128, 4 warps (2x2 of 64x64), BK=16, double-buffered.
// smem layout: [buf][kpair(8)][m(128), stride SST] packed bf16x2.
// =====================================================================
template<int AMODE, int EPI, bool DONORM>
__device__ __forceinline__ void gemm_core(
    uint32_t (&Ah)[2][8][SST], uint32_t (&Al)[2][8][SST],
    uint32_t (&Bh)[2][8][SST], uint32_t (&Bl)[2][8][SST],
    int bm, int bn,
    const float* __restrict__ x,  const float* __restrict__ W,
    const float* __restrict__ bias, const float* __restrict__ mix,
    const float* __restrict__ gnw, const float* __restrict__ gnb,
    float* __restrict__ out)
{
    const int tid  = threadIdx.x;
    const int lane = tid & 31;
    const int warp = tid >> 5;
    const int warpM = warp >> 1, warpN = warp & 1;

    const int lm  = tid >> 2;         // 0..31
    const int lk4 = (tid & 3) * 4;    // 0,4,8,12 (k offset within 16-wide stage)
    const int kp  = lk4 >> 1;         // kpair index: 0,2,4,6

    float c[4][8][4];
    #pragma unroll
    for (int i=0;i<4;i++)
        #pragma unroll
        for (int j=0;j<8;j++)
            #pragma unroll
            for (int q=0;q<4;q++) c[i][j][q]=0.f;

    float4 pa[4], pb[4];

    auto load_stage = [&](int kt){
        const int koff = kt*16 + lk4;
        #pragma unroll
        for (int i=0;i<4;i++){
            const int gm = bm*128 + lm + 32*i;
            if (AMODE==0){
                float4 xa = *(const float4*)(x + (size_t)gm*CDIM + koff);
                float4 mv = *(const float4*)(mix + koff);
                float4 xs = make_float4(0,0,0,0);
                if ((gm & (TSEQ-1)) != 0)
                    xs = *(const float4*)(x + (size_t)(gm-1)*CDIM + koff);
                pa[i].x = xa.x*mv.x + xs.x*(1.0f-mv.x);
                pa[i].y = xa.y*mv.y + xs.y*(1.0f-mv.y);
                pa[i].z = xa.z*mv.z + xs.z*(1.0f-mv.z);
                pa[i].w = xa.w*mv.w + xs.w*(1.0f-mv.w);
            } else {
                float4 w  = *(const float4*)(g_wkv + (size_t)gm*CDIM + koff);
                const int bh = (gm >> 11)*HHEAD + (koff >> 6);
                const float2 st = g_stats[bh];
                float4 gw = *(const float4*)(gnw + koff);
                float4 gb = *(const float4*)(gnb + koff);
                pa[i].x = (w.x - st.x)*st.y*gw.x + gb.x;
                pa[i].y = (w.y - st.x)*st.y*gw.y + gb.y;
                pa[i].z = (w.z - st.x)*st.y*gw.z + gb.z;
                pa[i].w = (w.w - st.x)*st.y*gw.w + gb.w;
            }
            const int gn = bn*128 + lm + 32*i;
            pb[i] = *(const float4*)(W + (size_t)gn*CDIM + koff);
        }
    };
    auto store_stage = [&](int buf){
        #pragma unroll
        for (int i=0;i<4;i++){
            const int m = lm + 32*i;
            uint32_t h0,l0,h1,l1;
            split_pack(pa[i].x, pa[i].y, h0, l0);
            split_pack(pa[i].z, pa[i].w, h1, l1);
            Ah[buf][kp  ][m]=h0; Al[buf][kp  ][m]=l0;
            Ah[buf][kp+1][m]=h1; Al[buf][kp+1][m]=l1;
            split_pack(pb[i].x, pb[i].y, h0, l0);
            split_pack(pb[i].z, pb[i].w, h1, l1);
            Bh[buf][kp  ][m]=h0; Bl[buf][kp  ][m]=l0;
            Bh[buf][kp+1][m]=h1; Bl[buf][kp+1][m]=l1;
        }
    };

    load_stage(0);

    const int g4 = lane >> 2;
    const int t4 = lane & 3;

    for (int kt=0; kt<CDIM/16; kt++){
        const int buf = kt & 1;
        store_stage(buf);
        __syncthreads();
        if (kt+1 < CDIM/16) load_stage(kt+1);

        // fragment loads: kpairs t4 (k=2t4,2t4+1) and t4+4 (k+8)
        uint32_t ah[4][4], al[4][4];
        #pragma unroll
        for (int mt=0; mt<4; mt++){
            const int m = warpM*64 + mt*16 + g4;
            ah[mt][0]=Ah[buf][t4  ][m];  al[mt][0]=Al[buf][t4  ][m];
            ah[mt][1]=Ah[buf][t4  ][m+8];al[mt][1]=Al[buf][t4  ][m+8];
            ah[mt][2]=Ah[buf][t4+4][m];  al[mt][2]=Al[buf][t4+4][m];
            ah[mt][3]=Ah[buf][t4+4][m+8];al[mt][3]=Al[buf][t4+4][m+8];
        }
        uint32_t bhf[8][2], blf[8][2];
        #pragma unroll
        for (int nt=0; nt<8; nt++){
            const int n = warpN*64 + nt*8 + g4;
            bhf[nt][0]=Bh[buf][t4  ][n]; blf[nt][0]=Bl[buf][t4  ][n];
            bhf[nt][1]=Bh[buf][t4+4][n]; blf[nt][1]=Bl[buf][t4+4][n];
        }
        #pragma unroll
        for (int mt=0; mt<4; mt++)
            #pragma unroll
            for (int nt=0; nt<8; nt++){
                mma_bf16(c[mt][nt], ah[mt], bhf[nt]);
                mma_bf16(c[mt][nt], ah[mt], blf[nt]);
                mma_bf16(c[mt][nt], al[mt], bhf[nt]);
            }
        __syncthreads();
    }

    // ---- epilogue ----
    #pragma unroll
    for (int mt=0; mt<4; mt++){
        const int r0 = bm*128 + warpM*64 + mt*16 + g4;
        const int r1 = r0 + 8;
        #pragma unroll
        for (int nt=0; nt<8; nt++){
            const int col = bn*128 + warpN*64 + nt*8 + t4*2;
            const float2 bb = *(const float2*)(bias + col);
            c[mt][nt][0] += bb.x; c[mt][nt][1] += bb.y;
            c[mt][nt][2] += bb.x; c[mt][nt][3] += bb.y;
        }
        float sc0 = 1.0f, sc1 = 1.0f;
        if (DONORM){
            float ss0=0.f, ss1=0.f;
            #pragma unroll
            for (int nt=0; nt<8; nt++){
                ss0 = fmaf(c[mt][nt][0],c[mt][nt][0], fmaf(c[mt][nt][1],c[mt][nt][1], ss0));
                ss1 = fmaf(c[mt][nt][2],c[mt][nt][2], fmaf(c[mt][nt][3],c[mt][nt][3], ss1));
            }
            ss0 += __shfl_xor_sync(0xffffffffu, ss0, 1);
            ss0 += __shfl_xor_sync(0xffffffffu, ss0, 2);
            ss1 += __shfl_xor_sync(0xffffffffu, ss1, 1);
            ss1 += __shfl_xor_sync(0xffffffffu, ss1, 2);
            sc0 = 1.0f/fmaxf(sqrtf(ss0), 1e-12f);
            sc1 = 1.0f/fmaxf(sqrtf(ss1), 1e-12f);
        }
        #pragma unroll
        for (int nt=0; nt<8; nt++){
            const int col = bn*128 + warpN*64 + nt*8 + t4*2;
            float v0 = c[mt][nt][0], v1 = c[mt][nt][1];
            float v2 = c[mt][nt][2], v3 = c[mt][nt][3];
            if (DONORM){ v0*=sc0; v1*=sc0; v2*=sc1; v3*=sc1; }
            if (EPI==EPI_SIG){ v0=sigf(v0); v1=sigf(v1); v2=sigf(v2); v3=sigf(v3); }
            else if (EPI==EPI_SILU){ v0*=sigf(v0); v1*=sigf(v1); v2*=sigf(v2); v3*=sigf(v3); }
            else if (EPI==EPI_GOUT){
                float2 g0 = *(const float2*)(g_g + (size_t)r0*CDIM + col);
                float2 g1 = *(const float2*)(g_g + (size_t)r1*CDIM + col);
                v0*=g0.x; v1*=g0.y; v2*=g1.x; v3*=g1.y;
            }
            *(float2*)(out + (size_t)r0*CDIM + col) = make_float2(v0,v1);
            *(float2*)(out + (size_t)r1*CDIM + col) = make_float2(v2,v3);
        }
    }
}

// ---------------- scan body: 1 CTA (128 thr) per (b,h) -------------------------
// (unchanged from R6 — isolates attribution of the bf16 GEMM switch)
__device__ __forceinline__ void scan_body(
    int bh, const float* __restrict__ decay, const float* __restrict__ eta,
    float* __restrict__ state_out)
{
    __shared__ __align__(16) float sk[2][64], sr[2][64], sv[2][64];
    __shared__ float red[2][4];
    __shared__ double redd[4][2];

    const int b = bh >> 4, h = bh & 15;
    const int t_ = threadIdx.x;
    const int row = t_ >> 1, half = t_ & 1;
    const int lane = t_ & 31, wid = t_ >> 5;
    const int koff = half*32;

    float S[32];
    #pragma unroll
    for (int j=0;j<32;j++) S[j]=0.f;
    float c = 1.0f;
    float ns = 0.f;
    const float dec = 1.0f/(1.0f+expf(-decay[h]));
    const float et  = 1.0f/(1.0f+expf(-eta[h]));
    const float maxn = 16.0f;
    double wsum = 0.0, wsq = 0.0;

    const size_t base = (size_t)b*TSEQ*CDIM + (size_t)h*64;
    const float* kp = g_k + base;
    const float* rp = g_r + base;
    const float* vp = g_v + base;
    float*       op = g_wkv + base;

    if (t_ < 64){ sk[0][t_] = kp[t_]; sv[0][t_] = vp[t_]; }
    else        { sr[0][t_-64] = rp[t_-64]; }
    float nk=0.f, nr=0.f, nv=0.f;
    if (t_ < 64){ nk = kp[CDIM+t_]; nv = vp[CDIM+t_]; }
    else        { nr = rp[CDIM+t_-64]; }
    __syncthreads();

    for (int t=0; t<TSEQ; t++){
        const int buf  = t & 1;
        const int nbuf = buf ^ 1;
        if (t+1 < TSEQ){
            if (t_ < 64){ sk[nbuf][t_]=nk; sv[nbuf][t_]=nv; }
            else        { sr[nbuf][t_-64]=nr; }
        }
        if (t+2 < TSEQ){
            if (t_ < 64){ nk = kp[2*CDIM+t_]; nv = vp[2*CDIM+t_]; }
            else        { nr = rp[2*CDIM+t_-64]; }
        }
        const float4* k4 = (const float4*)(&sk[buf][koff]);
        float q0=0,q1=0,q2=0,q3=0;
        #pragma unroll
        for (int j=0;j<8;j++){
            float4 kv = k4[j];
            q0 = fmaf(S[4*j+0], kv.x, q0);
            q1 = fmaf(S[4*j+1], kv.y, q1);
            q2 = fmaf(S[4*j+2], kv.z, q2);
            q3 = fmaf(S[4*j+3], kv.w, q3);
        }
        float qp = (q0+q1)+(q2+q3);
        qp += __shfl_xor_sync(0xffffffffu, qp, 1);
        const float vi   = sv[buf][row];
        const float err  = c*qp - vi;
        const float c1   = dec*c;
        const float coef = (et*err)/c1;
        const bool exact = ((t & 31) == 31);
        #pragma unroll
        for (int j=0;j<8;j++){
            float4 kv = k4[j];
            S[4*j+0] = fmaf(-coef, kv.x, S[4*j+0]);
            S[4*j+1] = fmaf(-coef, kv.y, S[4*j+1]);
            S[4*j+2] = fmaf(-coef, kv.z, S[4*j+2]);
            S[4*j+3] = fmaf(-coef, kv.w, S[4*j+3]);
        }
        float val;
        if (exact){
            float u0=0,u1=0,u2=0,u3=0;
            #pragma unroll
            for (int j=0;j<8;j++){
                u0 = fmaf(S[4*j+0],S[4*j+0],u0);
                u1 = fmaf(S[4*j+1],S[4*j+1],u1);
                u2 = fmaf(S[4*j+2],S[4*j+2],u2);
                u3 = fmaf(S[4*j+3],S[4*j+3],u3);
            }
            val = (u0+u1)+(u2+u3);
        } else {
            val = 0.5f*fmaf(coef, coef, -2.0f*coef*qp);
        }
        const float4* r4 = (const float4*)(&sr[buf][koff]);
        float w0=0,w1=0,w2=0,w3=0;
        #pragma unroll
        for (int j=0;j<8;j++){
            float4 rv = r4[j];
            w0 = fmaf(S[4*j+0], rv.x, w0);
            w1 = fmaf(S[4*j+1], rv.y, w1);
            w2 = fmaf(S[4*j+2], rv.z, w2);
            w3 = fmaf(S[4*j+3], rv.w, w3);
        }
        #pragma unroll
        for (int o=16;o;o>>=1) val += __shfl_xor_sync(0xffffffffu, val, o);
        if (lane==0) red[buf][wid]=val;
        float wpart = (w0+w1)+(w2+w3);
        wpart += __shfl_xor_sync(0xffffffffu, wpart, 1);
        __syncthreads();
        const float tot = red[buf][0]+red[buf][1]+red[buf][2]+red[buf][3];
        ns = exact ? tot : fmaxf(ns + tot, 0.f);
        const float nrm = c1*sqrtf(ns);
        c = (nrm > maxn) ? c1*(maxn/nrm) : c1;
        const float wv = c*wpart;
        if (half==0) op[row] = wv;
        wsum += (double)wv;
        wsq  += (double)wv*(double)wv;
        if (exact){
            #pragma unroll
            for (int j=0;j<32;j++) S[j]*=c;
            ns *= c*c;
            c = 1.0f;
        }
        kp += CDIM; rp += CDIM; vp += CDIM; op += CDIM;
    }
    double a1=wsum, a2=wsq;
    #pragma unroll
    for (int o=16;o;o>>=1){
        a1 += __shfl_xor_sync(0xffffffffu, a1, o);
        a2 += __shfl_xor_sync(0xffffffffu, a2, o);
    }
    if (lane==0){ redd[wid][0]=a1; redd[wid][1]=a2; }
    __syncthreads();
    if (t_==0){
        const double t1 = redd[0][0]+redd[1][0]+redd[2][0]+redd[3][0];
        const double t2 = redd[0][1]+redd[1][1]+redd[2][1]+redd[3][1];
        const double cnt = 2.0*(double)TSEQ*64.0;
        const double mean = t1 / cnt;
        const double var  = t2 / cnt - mean*mean;
        g_stats[bh] = make_float2((float)mean, (float)(1.0/sqrt(var + 1e-5)));
    }
    float* so = state_out ? state_out : g_state_scratch;
    #pragma unroll
    for (int j=0;j<32;j++)
        so[(size_t)bh*4096 + (size_t)row*64 + koff + j] = c*S[j];
}

// ---------------- kernels ------------------------------------------------------

// r/k/v projections (z picks projection)
__global__ __launch_bounds__(128, 2)
void proj_kernel(const float* __restrict__ x,
                 const float* __restrict__ W_r, const float* __restrict__ W_k,
                 const float* __restrict__ W_v,
                 const float* __restrict__ b_r, const float* __restrict__ b_k,
                 const float* __restrict__ b_v,
                 const float* __restrict__ mr, const float* __restrict__ mk,
                 const float* __restrict__ mv)
{
    __shared__ uint32_t Ah[2][8][SST], Al[2][8][SST];
    __shared__ uint32_t Bh[2][8][SST], Bl[2][8][SST];
    const int bm = blockIdx.y, bn = blockIdx.x, z = blockIdx.z;
    if (z==0)
        gemm_core<0,EPI_SIG, false>(Ah,Al,Bh,Bl,bm,bn, x, W_r, b_r, mr, nullptr,nullptr, g_r);
    else if (z==1)
        gemm_core<0,EPI_NONE,true >(Ah,Al,Bh,Bl,bm,bn, x, W_k, b_k, mk, nullptr,nullptr, g_k);
    else
        gemm_core<0,EPI_NONE,true >(Ah,Al,Bh,Bl,bm,bn, x, W_v, b_v, mv, nullptr,nullptr, g_v);
}

// merged: scan (CTAs 0..127) + g projection (CTAs 128..1151)
__global__ __launch_bounds__(128, 2)
void scan_g_kernel(const float* __restrict__ x,
                   const float* __restrict__ W_g, const float* __restrict__ b_g,
                   const float* __restrict__ mg,
                   const float* __restrict__ decay, const float* __restrict__ eta,
                   float* __restrict__ state_out)
{
    __shared__ uint32_t Ah[2][8][SST], Al[2][8][SST];
    __shared__ uint32_t Bh[2][8][SST], Bl[2][8][SST];
    if (blockIdx.x < 128){
        scan_body(blockIdx.x, decay, eta, state_out);
    } else {
        const int bi = blockIdx.x - 128;
        gemm_core<0,EPI_SILU,false>(Ah,Al,Bh,Bl, bi>>3, bi&7, x, W_g, b_g, mg,
                                    nullptr,nullptr, g_g);
    }
}

// output projection: groupnorm fused into A-loader, *g in epilogue
__global__ __launch_bounds__(128, 2)
void outproj_kernel(const float* __restrict__ W_o, const float* __restrict__ b_o,
                    const float* __restrict__ gnw, const float* __restrict__ gnb,
                    float* __restrict__ out)
{
    __shared__ uint32_t Ah[2][8][SST], Al[2][8][SST];
    __shared__ uint32_t Bh[2][8][SST], Bl[2][8][SST];
    gemm_core<1,EPI_GOUT,false>(Ah,Al,Bh,Bl, blockIdx.y, blockIdx.x,
                                nullptr, W_o, b_o, nullptr, gnw, gnb, out);
}

// last_x = x[:, -1, :]
__global__ void lastx_kernel(const float* __restrict__ x, float* __restrict__ outp)
{
    const int i = blockIdx.x*blockDim.x + threadIdx.x;
    if (i >= BBAT*CDIM) return;
    const int b  = i >> 10;
    const int cc = i & (CDIM-1);
    outp[i] = x[((size_t)b*TSEQ + (TSEQ-1))*CDIM + cc];
}

// ---------------- launch --------------------------------------------------------
extern "C" void kernel_launch(void* const* d_in, const int* in_sizes, int n_in,
                              void* d_out, int out_size)
{
    const float* x    = (const float*)d_in[0];
    const float* W_r  = (const float*)d_in[1];
    const float* b_r  = (const float*)d_in[2];
    const float* W_k  = (const float*)d_in[3];
    const float* b_k  = (const float*)d_in[4];
    const float* W_v  = (const float*)d_in[5];
    const float* b_v  = (const float*)d_in[6];
    const float* W_g  = (const float*)d_in[7];
    const float* b_g  = (const float*)d_in[8];
    const float* W_o  = (const float*)d_in[9];
    const float* b_o  = (const float*)d_in[10];
    const float* decay= (const float*)d_in[11];
    const float* eta  = (const float*)d_in[12];
    const float* mixr = (const float*)d_in[13];
    const float* mixk = (const float*)d_in[14];
    const float* mixv = (const float*)d_in[15];
    const float* mixg = (const float*)d_in[16];
    const float* gnw  = (const float*)d_in[17];
    const float* gnb  = (const float*)d_in[18];
    float* out = (float*)d_out;

    const int MAIN  = MROWS*CDIM;
    const int STATE = BBAT*HHEAD*64*64;
    const int LASTX = BBAT*CDIM;
    const bool full = out_size >= MAIN + STATE + LASTX;

    proj_kernel<<<dim3(8,128,3),128>>>(x, W_r,W_k,W_v, b_r,b_k,b_v, mixr,mixk,mixv);
    scan_g_kernel<<<128+1024,128>>>(x, W_g, b_g, mixg, decay, eta,
                                    full ? (out + MAIN) : nullptr);
    outproj_kernel<<<dim3(8,128),128>>>(W_o, b_o, gnw, gnb, out);
    if (full) lastx_kernel<<<32,256>>>(x, out + MAIN + STATE);
}